// round 13
// baseline (speedup 1.0000x reference)
#include <cuda_runtime.h>

// Inputs: q, r, Ek, Ev, Mk, Mv0, We, be, Wa, ba, Wf, bf, Wp, bp
// q,r int32 [64,512]; rest float32. Output: p [64,512] float32.

#define NUM_C 1000
#define DIM   128
#define MSZ   64
#define BB    64
#define LL    512
#define NTOK  (BB*LL)

typedef unsigned long long ull;

// ---------------- device scratch ----------------
__device__ float g_w  [NUM_C*MSZ];       // softmax(Ek[q] @ Mk^T)        [1000,64]
__device__ float g_nea[2*NUM_C*DIM*2];   // interleaved [x][64][ne0,ne1,a0,a1] (ne negated)
__device__ float g_fk [NUM_C*DIM];       // Ek@Wf[128:256] + bf          [1000,128]
__device__ float g_read[NTOK*DIM];       // scan output                  [B*L,128]

// ---------------- f32x2 helpers ----------------
__device__ __forceinline__ ull fma2(ull a, ull b, ull c) {
    ull d; asm("fma.rn.f32x2 %0, %1, %2, %3;" : "=l"(d) : "l"(a), "l"(b), "l"(c)); return d;
}
__device__ __forceinline__ ull add2(ull a, ull b) {
    ull d; asm("add.rn.f32x2 %0, %1, %2;" : "=l"(d) : "l"(a), "l"(b)); return d;
}
__device__ __forceinline__ ull pack2(float x, float y) {
    ull d; asm("mov.b64 %0, {%1, %2};" : "=l"(d) : "f"(x), "f"(y)); return d;
}
__device__ __forceinline__ float2 unpack2(ull v) {
    float2 r; asm("mov.b64 {%0, %1}, %2;" : "=f"(r.x), "=f"(r.y) : "l"(v)); return r;
}
__device__ __forceinline__ float sigmoid_fast(float x) {
    return __fdividef(1.0f, 1.0f + __expf(-x));
}
__device__ __forceinline__ float tanh_fast(float x) {
    return 1.0f - __fdividef(2.0f, __expf(2.0f * x) + 1.0f);
}

// ======================================================================
// Kernel 1a: softmax correlation-weight table. 50 blocks x 10 q-pairs.
// (33KB smem — isolated so it doesn't tax cgemm occupancy.)
// ======================================================================
#define WT_BLOCKS 50
#define WT_PAIRS  10

__global__ void __launch_bounds__(128) k_wtab(const float* __restrict__ Ek,
                                              const float* __restrict__ Mk) {
    __shared__ float mk[MSZ][DIM + 2];
    __shared__ float ek[2][2][DIM];
    __shared__ float xmax[2][4];
    __shared__ float xsum[2][4];

    int bid = blockIdx.x, t = threadIdx.x;
    int h = t >> 6, m = t & 63;
    int lane = t & 31, wid = t >> 5;

    for (int idx = t; idx < MSZ * DIM; idx += 128)
        mk[idx >> 7][idx & 127] = Mk[idx];
    __syncthreads();

    ull mk2[64];
#pragma unroll
    for (int j = 0; j < 64; j++)
        mk2[j] = pack2(mk[m][2*j], mk[m][2*j + 1]);

    int qp0 = bid * WT_PAIRS;
    float e0 = Ek[(2*qp0)*DIM + t];
    float e1 = Ek[(2*qp0 + 1)*DIM + t];
    int pb = 0;
    for (int i = 0; i < WT_PAIRS; i++) {
        ek[pb][0][t] = e0;
        ek[pb][1][t] = e1;
        __syncthreads();
        if (i + 1 < WT_PAIRS) {
            e0 = Ek[(2*(qp0 + i + 1))*DIM + t];
            e1 = Ek[(2*(qp0 + i + 1) + 1)*DIM + t];
        }
        const ull* ep = (const ull*)ek[pb][h];
        ull a0 = 0ULL, a1 = 0ULL;
#pragma unroll
        for (int j = 0; j < 64; j += 2) {
            a0 = fma2(ep[j],   mk2[j],   a0);
            a1 = fma2(ep[j+1], mk2[j+1], a1);
        }
        float2 ac = unpack2(add2(a0, a1));
        float lv = ac.x + ac.y;

        float wm = lv;
#pragma unroll
        for (int o = 16; o > 0; o >>= 1)
            wm = fmaxf(wm, __shfl_xor_sync(0xffffffffu, wm, o));
        if (lane == 0) xmax[pb][wid] = wm;
        __syncthreads();
        float mx = fmaxf(xmax[pb][h*2], xmax[pb][h*2 + 1]);
        float ev = __expf(lv - mx);
        float ws = ev;
#pragma unroll
        for (int o = 16; o > 0; o >>= 1)
            ws += __shfl_xor_sync(0xffffffffu, ws, o);
        if (lane == 0) xsum[pb][wid] = ws;
        __syncthreads();
        float s = xsum[pb][h*2] + xsum[pb][h*2 + 1];
        g_w[(2*(qp0 + i) + h)*MSZ + m] = __fdividef(ev, s);
        pb ^= 1;
    }
}

// ======================================================================
// Kernel 1b: column-GEMM tables, 250 blocks x 20 rows (2 rows/iter).
// 1KB smem -> full occupancy. Interleaved g_nea output.
// ======================================================================
__global__ void __launch_bounds__(128) k_cgemm(
        const float* __restrict__ Ek, const float* __restrict__ Ev,
        const float* __restrict__ We, const float* __restrict__ be,
        const float* __restrict__ Wa, const float* __restrict__ ba,
        const float* __restrict__ Wf, const float* __restrict__ bf) {
    __shared__ __align__(16) float sv[2][DIM];
    int cb = blockIdx.x, t = threadIdx.x;
    const float *W, *bias, *rows;
    int mode, row0;
    if (cb < 100)      { W = We;           bias = be; rows = Ev; mode = 0; row0 = cb*20; }
    else if (cb < 200) { W = Wa;           bias = ba; rows = Ev; mode = 1; row0 = (cb-100)*20; }
    else               { W = Wf + DIM*DIM; bias = bf; rows = Ek; mode = 2; row0 = (cb-200)*20; }

    ull w2[64];
#pragma unroll
    for (int j = 0; j < 64; j++)
        w2[j] = pack2(W[(2*j)*DIM + t], W[(2*j+1)*DIM + t]);
    float bv = bias[t];

    int ofs = (t >> 1)*4 + (t & 1) + ((mode == 1) ? 2 : 0);

    float nA = rows[row0*DIM + t];
    float nB = rows[(row0 + 1)*DIM + t];
    for (int i = 0; i < 10; i++) {
        sv[0][t] = nA;
        sv[1][t] = nB;
        __syncthreads();
        if (i < 9) {
            nA = rows[(row0 + 2*i + 2)*DIM + t];
            nB = rows[(row0 + 2*i + 3)*DIM + t];
        }
        const ull* sa = (const ull*)sv[0];
        const ull* sb = (const ull*)sv[1];
        ull aA0 = pack2(bv, 0.f), aA1 = 0ULL;
        ull aB0 = pack2(bv, 0.f), aB1 = 0ULL;
#pragma unroll
        for (int j = 0; j < 64; j += 2) {
            aA0 = fma2(sa[j],   w2[j],   aA0);
            aA1 = fma2(sa[j+1], w2[j+1], aA1);
            aB0 = fma2(sb[j],   w2[j],   aB0);
            aB1 = fma2(sb[j+1], w2[j+1], aB1);
        }
        float2 fA = unpack2(add2(aA0, aA1));
        float2 fB = unpack2(add2(aB0, aB1));
        float gA = fA.x + fA.y, gB = fB.x + fB.y;
        int rA = row0 + 2*i, rB = rA + 1;
        if (mode == 0) {
            g_nea[rA*256 + ofs] = -sigmoid_fast(gA);
            g_nea[rB*256 + ofs] = -sigmoid_fast(gB);
        } else if (mode == 1) {
            g_nea[rA*256 + ofs] = tanh_fast(gA);
            g_nea[rB*256 + ofs] = tanh_fast(gB);
        } else {
            g_fk[rA*DIM + t] = gA;
            g_fk[rB*DIM + t] = gB;
        }
        __syncthreads();
    }
}

// ======================================================================
// Kernel 2: barrier-free scan (r11 form — near its FP32-pipe floor).
// ======================================================================
struct SD { float w[16]; ull ne2, a2; };

__device__ __forceinline__ void sd_load(SD& s, int2 ix, int mq, int cpIdx) {
    const float4* wp = (const float4*)(g_w + ix.x + mq*16);
    float4 w0 = wp[0], w1 = wp[1], w2 = wp[2], w3 = wp[3];
    s.w[0]=w0.x; s.w[1]=w0.y; s.w[2]=w0.z; s.w[3]=w0.w;
    s.w[4]=w1.x; s.w[5]=w1.y; s.w[6]=w1.z; s.w[7]=w1.w;
    s.w[8]=w2.x; s.w[9]=w2.y; s.w[10]=w2.z; s.w[11]=w2.w;
    s.w[12]=w3.x; s.w[13]=w3.y; s.w[14]=w3.z; s.w[15]=w3.w;
    ulonglong2 v = *(const ulonglong2*)(g_nea + (ix.y + cpIdx)*4);
    s.ne2 = v.x;
    s.a2  = v.y;
}

__device__ __forceinline__ ull scan_fma(const SD& s, ull mv[16]) {
    ull r0 = 0ULL, r1 = 0ULL;
#pragma unroll
    for (int j = 0; j < 16; j++) {
        ull w2 = pack2(s.w[j], s.w[j]);
        ull tt = fma2(mv[j], s.ne2, s.a2);
        if (j & 1) r1 = fma2(w2, mv[j], r1);
        else       r0 = fma2(w2, mv[j], r0);
        mv[j] = fma2(w2, tt, mv[j]);
    }
    return add2(r0, r1);
}

__global__ void __launch_bounds__(128, 1) k_scan(const float* __restrict__ Mv0,
                                                 const int* __restrict__ q,
                                                 const int* __restrict__ r) {
    __shared__ int2 sidx[LL];
    int bx = blockIdx.x, b = bx >> 1, h = bx & 1;
    int tid = threadIdx.x, wid = tid >> 5, lane = tid & 31;
    int mq = lane >> 3, cpi = lane & 7;

    for (int i = tid; i < LL; i += 128) {
        int qv = q[b*LL + i], rv = r[b*LL + i];
        sidx[i] = make_int2(qv*MSZ, (qv + NUM_C*rv)*64);
    }

    int eoff  = h*64 + wid*16 + cpi*2;
    int cpIdx = eoff >> 1;
    ull mv[16];
#pragma unroll
    for (int j = 0; j < 16; j++)
        mv[j] = *(const ull*)(Mv0 + (mq*16 + j)*DIM + eoff);
    __syncthreads();

    float* rb = g_read + (b*LL)*DIM + eoff;

    SD S[8];
#pragma unroll
    for (int i = 0; i < 8; i++) sd_load(S[i], sidx[i], mq, cpIdx);
    int2 nix = sidx[8];

    ull racc_p = 0ULL, s1_p = 0ULL, r2_p = 0ULL, s2_p = 0ULL;

    for (int l = 0; l < LL; l += 8) {
#pragma unroll
        for (int u = 0; u < 8; u++) {
            int lc = l + u;
            ull racc = scan_fma(S[u], mv);
            sd_load(S[u], nix, mq, cpIdx);
            int nl = lc + 9;
            nix = sidx[(nl < LL) ? nl : (LL - 1)];
            ull r2n = add2(racc_p, s1_p);
            ull s2n = __shfl_xor_sync(0xffffffffu, r2n, 16);
            ull fin = add2(r2_p, s2_p);
            if (lc >= 2 && mq == 0) *(ull*)(rb + (lc - 2)*DIM) = fin;
            ull s1n = __shfl_xor_sync(0xffffffffu, racc, 8);
            racc_p = racc; s1_p = s1n; r2_p = r2n; s2_p = s2n;
        }
    }
    ull r2n = add2(racc_p, s1_p);
    ull s2n = __shfl_xor_sync(0xffffffffu, r2n, 16);
    ull fin = add2(r2_p, s2_p);
    if (mq == 0) *(ull*)(rb + 510*DIM) = fin;
    fin = add2(r2n, s2n);
    if (mq == 0) *(ull*)(rb + 511*DIM) = fin;
}

// ======================================================================
// Kernel 3: f = tanh(read@Wf_r + fk), p = sigmoid(f.Wp + bp).
// r12 form: ONE bar/iter, deferred epilogue, fk folded into partials.
// ======================================================================
__global__ void __launch_bounds__(128, 2) k_fp(const int* __restrict__ q,
                                               const float* __restrict__ Wf,
                                               const float* __restrict__ Wp,
                                               const float* __restrict__ bp,
                                               float* __restrict__ out) {
    __shared__ __align__(16) ull rr[2][8][DIM];             // 16KB
    __shared__ __align__(16) ulonglong2 part[2][8][4][32];  // 32KB
    int tid = threadIdx.x;
    int iq = tid >> 5, po = tid & 31;

    ull wfA[32], wfB[32];
#pragma unroll
    for (int i = 0; i < 32; i++) {
        wfA[i] = *(const ull*)(Wf + (iq*32 + i)*DIM + 2*po);
        wfB[i] = *(const ull*)(Wf + (iq*32 + i)*DIM + 64 + 2*po);
    }
    float wp0 = Wp[2*po],      wp1 = Wp[2*po + 1];
    float wp2 = Wp[2*po + 64], wp3 = Wp[2*po + 65];
    float bpv = bp[0];

    const int stride = gridDim.x * 8;
    const int start = blockIdx.x * 8;

    float rv[8];
    ull fkA0 = 0ULL, fkA1 = 0ULL, fkB0 = 0ULL, fkB1 = 0ULL;
    if (start < NTOK) {
#pragma unroll
        for (int tt = 0; tt < 8; tt++)
            rv[tt] = g_read[(start + tt)*DIM + tid];
        int q0 = q[start + 2*iq], q1 = q[start + 2*iq + 1];
        fkA0 = *(const ull*)(g_fk + q0*DIM + 2*po);
        fkA1 = *(const ull*)(g_fk + q0*DIM + 2*po + 64);
        fkB0 = *(const ull*)(g_fk + q1*DIM + 2*po);
        fkB1 = *(const ull*)(g_fk + q1*DIM + 2*po + 64);
    }

    int pb = 0;
    int tok0 = start;
    for (; tok0 < NTOK; tok0 += stride) {
#pragma unroll
        for (int tt = 0; tt < 8; tt++)
            rr[pb][tt][tid] = pack2(rv[tt], rv[tt]);
        __syncthreads();                               // the ONLY bar

        int tokn = tok0 + stride;
        float rvn[8];
        ull fkA0n = 0ULL, fkA1n = 0ULL, fkB0n = 0ULL, fkB1n = 0ULL;
        if (tokn < NTOK) {
#pragma unroll
            for (int tt = 0; tt < 8; tt++)
                rvn[tt] = g_read[(tokn + tt)*DIM + tid];
            int qn0 = q[tokn + 2*iq], qn1 = q[tokn + 2*iq + 1];
            fkA0n = *(const ull*)(g_fk + qn0*DIM + 2*po);
            fkA1n = *(const ull*)(g_fk + qn0*DIM + 2*po + 64);
            fkB0n = *(const ull*)(g_fk + qn1*DIM + 2*po);
            fkB1n = *(const ull*)(g_fk + qn1*DIM + 2*po + 64);
        } else {
#pragma unroll
            for (int tt = 0; tt < 8; tt++) rvn[tt] = 0.f;
        }

        ull accA[8], accB[8];
#pragma unroll
        for (int tt = 0; tt < 8; tt++) { accA[tt] = 0ULL; accB[tt] = 0ULL; }
#pragma unroll
        for (int j = 0; j < 16; j++) {
#pragma unroll
            for (int tt = 0; tt < 8; tt++) {
                ulonglong2 v = ((const ulonglong2*)&rr[pb][tt][iq*32])[j];
                accA[tt] = fma2(wfA[2*j],     v.x, accA[tt]);
                accA[tt] = fma2(wfA[2*j + 1], v.y, accA[tt]);
                accB[tt] = fma2(wfB[2*j],     v.x, accB[tt]);
                accB[tt] = fma2(wfB[2*j + 1], v.y, accB[tt]);
            }
        }
        accA[2*iq]     = add2(accA[2*iq],     fkA0);
        accB[2*iq]     = add2(accB[2*iq],     fkA1);
        accA[2*iq + 1] = add2(accA[2*iq + 1], fkB0);
        accB[2*iq + 1] = add2(accB[2*iq + 1], fkB1);
#pragma unroll
        for (int tt = 0; tt < 8; tt++) {
            ulonglong2 pr; pr.x = accA[tt]; pr.y = accB[tt];
            part[pb][tt][iq][po] = pr;
        }

        // deferred epilogue for PREVIOUS iteration (overlaps this GEMV)
        if (tok0 != start) {
            int tokp = tok0 - stride;
            int t0 = 2*iq, t1 = t0 + 1;
            ull sA0 = 0ULL, sA1 = 0ULL, sB0 = 0ULL, sB1 = 0ULL;
#pragma unroll
            for (int g4 = 0; g4 < 4; g4++) {
                ulonglong2 p0 = part[pb^1][t0][g4][po];
                ulonglong2 p1 = part[pb^1][t1][g4][po];
                sA0 = add2(sA0, p0.x);
                sA1 = add2(sA1, p0.y);
                sB0 = add2(sB0, p1.x);
                sB1 = add2(sB1, p1.y);
            }
            float2 a0 = unpack2(sA0), a1 = unpack2(sA1);
            float2 b0 = unpack2(sB0), b1 = unpack2(sB1);
            float pvA = fmaf(tanh_fast(a0.x), wp0,
                        fmaf(tanh_fast(a0.y), wp1,
                        fmaf(tanh_fast(a1.x), wp2, tanh_fast(a1.y) * wp3)));
            float pvB = fmaf(tanh_fast(b0.x), wp0,
                        fmaf(tanh_fast(b0.y), wp1,
                        fmaf(tanh_fast(b1.x), wp2, tanh_fast(b1.y) * wp3)));
#pragma unroll
            for (int o = 16; o > 0; o >>= 1) {
                pvA += __shfl_xor_sync(0xffffffffu, pvA, o);
                pvB += __shfl_xor_sync(0xffffffffu, pvB, o);
            }
            if (po == 0) {
                out[tokp + t0] = sigmoid_fast(pvA + bpv);
                out[tokp + t1] = sigmoid_fast(pvB + bpv);
            }
        }

        pb ^= 1;
#pragma unroll
        for (int tt = 0; tt < 8; tt++) rv[tt] = rvn[tt];
        fkA0 = fkA0n; fkA1 = fkA1n; fkB0 = fkB0n; fkB1 = fkB1n;
    }

    // drain: epilogue for the final iteration
    __syncthreads();
    if (start < NTOK) {
        int tokp = tok0 - stride;
        int t0 = 2*iq, t1 = t0 + 1;
        ull sA0 = 0ULL, sA1 = 0ULL, sB0 = 0ULL, sB1 = 0ULL;
#pragma unroll
        for (int g4 = 0; g4 < 4; g4++) {
            ulonglong2 p0 = part[pb^1][t0][g4][po];
            ulonglong2 p1 = part[pb^1][t1][g4][po];
            sA0 = add2(sA0, p0.x);
            sA1 = add2(sA1, p0.y);
            sB0 = add2(sB0, p1.x);
            sB1 = add2(sB1, p1.y);
        }
        float2 a0 = unpack2(sA0), a1 = unpack2(sA1);
        float2 b0 = unpack2(sB0), b1 = unpack2(sB1);
        float pvA = fmaf(tanh_fast(a0.x), wp0,
                    fmaf(tanh_fast(a0.y), wp1,
                    fmaf(tanh_fast(a1.x), wp2, tanh_fast(a1.y) * wp3)));
        float pvB = fmaf(tanh_fast(b0.x), wp0,
                    fmaf(tanh_fast(b0.y), wp1,
                    fmaf(tanh_fast(b1.x), wp2, tanh_fast(b1.y) * wp3)));
#pragma unroll
        for (int o = 16; o > 0; o >>= 1) {
            pvA += __shfl_xor_sync(0xffffffffu, pvA, o);
            pvB += __shfl_xor_sync(0xffffffffu, pvB, o);
        }
        if (po == 0) {
            out[tokp + t0] = sigmoid_fast(pvA + bpv);
            out[tokp + t1] = sigmoid_fast(pvB + bpv);
        }
    }
}

// ---------------- launch ----------------
extern "C" void kernel_launch(void* const* d_in, const int* in_sizes, int n_in,
                              void* d_out, int out_size) {
    const int*   q   = (const int*)d_in[0];
    const int*   r   = (const int*)d_in[1];
    const float* Ek  = (const float*)d_in[2];
    const float* Ev  = (const float*)d_in[3];
    const float* Mk  = (const float*)d_in[4];
    const float* Mv0 = (const float*)d_in[5];
    const float* We  = (const float*)d_in[6];
    const float* be  = (const float*)d_in[7];
    const float* Wa  = (const float*)d_in[8];
    const float* ba  = (const float*)d_in[9];
    const float* Wf  = (const float*)d_in[10];
    const float* bf  = (const float*)d_in[11];
    const float* Wp  = (const float*)d_in[12];
    const float* bp  = (const float*)d_in[13];
    float* out = (float*)d_out;

    k_wtab<<<WT_BLOCKS, 128>>>(Ek, Mk);
    k_cgemm<<<250, 128>>>(Ek, Ev, We, be, Wa, ba, Wf, bf);
    k_scan<<<2*BB, 128>>>(Mv0, q, r);
    k_fp<<<296, 128>>>(q, Wf, Wp, bp, out);
}

// round 14
// speedup vs baseline: 1.0726x; 1.0726x over previous
#include <cuda_runtime.h>

// Inputs: q, r, Ek, Ev, Mk, Mv0, We, be, Wa, ba, Wf, bf, Wp, bp
// q,r int32 [64,512]; rest float32. Output: p [64,512] float32.

#define NUM_C 1000
#define DIM   128
#define MSZ   64
#define BB    64
#define LL    512
#define NTOK  (BB*LL)

typedef unsigned long long ull;

// ---------------- device scratch ----------------
__device__ float g_w  [NUM_C*MSZ];       // softmax(Ek[q] @ Mk^T)        [1000,64]
__device__ float g_nea[2*NUM_C*DIM*2];   // interleaved [x][64][ne0,ne1,a0,a1] (ne negated)
__device__ float g_fk [NUM_C*DIM];       // Ek@Wf[128:256] + bf          [1000,128]
__device__ float g_read[NTOK*DIM];       // scan output                  [B*L,128]

// ---------------- f32x2 helpers ----------------
__device__ __forceinline__ ull fma2(ull a, ull b, ull c) {
    ull d; asm("fma.rn.f32x2 %0, %1, %2, %3;" : "=l"(d) : "l"(a), "l"(b), "l"(c)); return d;
}
__device__ __forceinline__ ull add2(ull a, ull b) {
    ull d; asm("add.rn.f32x2 %0, %1, %2;" : "=l"(d) : "l"(a), "l"(b)); return d;
}
__device__ __forceinline__ ull pack2(float x, float y) {
    ull d; asm("mov.b64 %0, {%1, %2};" : "=l"(d) : "f"(x), "f"(y)); return d;
}
__device__ __forceinline__ float2 unpack2(ull v) {
    float2 r; asm("mov.b64 {%0, %1}, %2;" : "=f"(r.x), "=f"(r.y) : "l"(v)); return r;
}
__device__ __forceinline__ float sigmoid_fast(float x) {
    return __fdividef(1.0f, 1.0f + __expf(-x));
}
__device__ __forceinline__ float tanh_fast(float x) {
    return 1.0f - __fdividef(2.0f, __expf(2.0f * x) + 1.0f);
}

// ======================================================================
// Kernel 1a: softmax correlation-weight table. 50 blocks x 10 q-pairs.
// ======================================================================
#define WT_BLOCKS 50
#define WT_PAIRS  10

__global__ void __launch_bounds__(128) k_wtab(const float* __restrict__ Ek,
                                              const float* __restrict__ Mk) {
    __shared__ float mk[MSZ][DIM + 2];
    __shared__ float ek[2][2][DIM];
    __shared__ float xmax[2][4];
    __shared__ float xsum[2][4];

    int bid = blockIdx.x, t = threadIdx.x;
    int h = t >> 6, m = t & 63;
    int lane = t & 31, wid = t >> 5;

    for (int idx = t; idx < MSZ * DIM; idx += 128)
        mk[idx >> 7][idx & 127] = Mk[idx];
    __syncthreads();

    ull mk2[64];
#pragma unroll
    for (int j = 0; j < 64; j++)
        mk2[j] = pack2(mk[m][2*j], mk[m][2*j + 1]);

    int qp0 = bid * WT_PAIRS;
    float e0 = Ek[(2*qp0)*DIM + t];
    float e1 = Ek[(2*qp0 + 1)*DIM + t];
    int pb = 0;
    for (int i = 0; i < WT_PAIRS; i++) {
        ek[pb][0][t] = e0;
        ek[pb][1][t] = e1;
        __syncthreads();
        if (i + 1 < WT_PAIRS) {
            e0 = Ek[(2*(qp0 + i + 1))*DIM + t];
            e1 = Ek[(2*(qp0 + i + 1) + 1)*DIM + t];
        }
        const ull* ep = (const ull*)ek[pb][h];
        ull a0 = 0ULL, a1 = 0ULL;
#pragma unroll
        for (int j = 0; j < 64; j += 2) {
            a0 = fma2(ep[j],   mk2[j],   a0);
            a1 = fma2(ep[j+1], mk2[j+1], a1);
        }
        float2 ac = unpack2(add2(a0, a1));
        float lv = ac.x + ac.y;

        float wm = lv;
#pragma unroll
        for (int o = 16; o > 0; o >>= 1)
            wm = fmaxf(wm, __shfl_xor_sync(0xffffffffu, wm, o));
        if (lane == 0) xmax[pb][wid] = wm;
        __syncthreads();
        float mx = fmaxf(xmax[pb][h*2], xmax[pb][h*2 + 1]);
        float ev = __expf(lv - mx);
        float ws = ev;
#pragma unroll
        for (int o = 16; o > 0; o >>= 1)
            ws += __shfl_xor_sync(0xffffffffu, ws, o);
        if (lane == 0) xsum[pb][wid] = ws;
        __syncthreads();
        float s = xsum[pb][h*2] + xsum[pb][h*2 + 1];
        g_w[(2*(qp0 + i) + h)*MSZ + m] = __fdividef(ev, s);
        pb ^= 1;
    }
}

// ======================================================================
// Kernel 1b: column-GEMM tables, 250 blocks x 20 rows (2 rows/iter).
// ======================================================================
__global__ void __launch_bounds__(128) k_cgemm(
        const float* __restrict__ Ek, const float* __restrict__ Ev,
        const float* __restrict__ We, const float* __restrict__ be,
        const float* __restrict__ Wa, const float* __restrict__ ba,
        const float* __restrict__ Wf, const float* __restrict__ bf) {
    __shared__ __align__(16) float sv[2][DIM];
    int cb = blockIdx.x, t = threadIdx.x;
    const float *W, *bias, *rows;
    int mode, row0;
    if (cb < 100)      { W = We;           bias = be; rows = Ev; mode = 0; row0 = cb*20; }
    else if (cb < 200) { W = Wa;           bias = ba; rows = Ev; mode = 1; row0 = (cb-100)*20; }
    else               { W = Wf + DIM*DIM; bias = bf; rows = Ek; mode = 2; row0 = (cb-200)*20; }

    ull w2[64];
#pragma unroll
    for (int j = 0; j < 64; j++)
        w2[j] = pack2(W[(2*j)*DIM + t], W[(2*j+1)*DIM + t]);
    float bv = bias[t];

    int ofs = (t >> 1)*4 + (t & 1) + ((mode == 1) ? 2 : 0);

    float nA = rows[row0*DIM + t];
    float nB = rows[(row0 + 1)*DIM + t];
    for (int i = 0; i < 10; i++) {
        sv[0][t] = nA;
        sv[1][t] = nB;
        __syncthreads();
        if (i < 9) {
            nA = rows[(row0 + 2*i + 2)*DIM + t];
            nB = rows[(row0 + 2*i + 3)*DIM + t];
        }
        const ull* sa = (const ull*)sv[0];
        const ull* sb = (const ull*)sv[1];
        ull aA0 = pack2(bv, 0.f), aA1 = 0ULL;
        ull aB0 = pack2(bv, 0.f), aB1 = 0ULL;
#pragma unroll
        for (int j = 0; j < 64; j += 2) {
            aA0 = fma2(sa[j],   w2[j],   aA0);
            aA1 = fma2(sa[j+1], w2[j+1], aA1);
            aB0 = fma2(sb[j],   w2[j],   aB0);
            aB1 = fma2(sb[j+1], w2[j+1], aB1);
        }
        float2 fA = unpack2(add2(aA0, aA1));
        float2 fB = unpack2(add2(aB0, aB1));
        float gA = fA.x + fA.y, gB = fB.x + fB.y;
        int rA = row0 + 2*i, rB = rA + 1;
        if (mode == 0) {
            g_nea[rA*256 + ofs] = -sigmoid_fast(gA);
            g_nea[rB*256 + ofs] = -sigmoid_fast(gB);
        } else if (mode == 1) {
            g_nea[rA*256 + ofs] = tanh_fast(gA);
            g_nea[rB*256 + ofs] = tanh_fast(gB);
        } else {
            g_fk[rA*DIM + t] = gA;
            g_fk[rB*DIM + t] = gB;
        }
        __syncthreads();
    }
}

// ======================================================================
// Kernel 2: barrier-free scan (r11 measured form, unchanged).
// ======================================================================
struct SD { float w[16]; ull ne2, a2; };

__device__ __forceinline__ void sd_load(SD& s, int2 ix, int mq, int cpIdx) {
    const float4* wp = (const float4*)(g_w + ix.x + mq*16);
    float4 w0 = wp[0], w1 = wp[1], w2 = wp[2], w3 = wp[3];
    s.w[0]=w0.x; s.w[1]=w0.y; s.w[2]=w0.z; s.w[3]=w0.w;
    s.w[4]=w1.x; s.w[5]=w1.y; s.w[6]=w1.z; s.w[7]=w1.w;
    s.w[8]=w2.x; s.w[9]=w2.y; s.w[10]=w2.z; s.w[11]=w2.w;
    s.w[12]=w3.x; s.w[13]=w3.y; s.w[14]=w3.z; s.w[15]=w3.w;
    ulonglong2 v = *(const ulonglong2*)(g_nea + (ix.y + cpIdx)*4);
    s.ne2 = v.x;
    s.a2  = v.y;
}

__device__ __forceinline__ ull scan_fma(const SD& s, ull mv[16]) {
    ull r0 = 0ULL, r1 = 0ULL;
#pragma unroll
    for (int j = 0; j < 16; j++) {
        ull w2 = pack2(s.w[j], s.w[j]);
        ull tt = fma2(mv[j], s.ne2, s.a2);
        if (j & 1) r1 = fma2(w2, mv[j], r1);
        else       r0 = fma2(w2, mv[j], r0);
        mv[j] = fma2(w2, tt, mv[j]);
    }
    return add2(r0, r1);
}

__global__ void __launch_bounds__(128, 1) k_scan(const float* __restrict__ Mv0,
                                                 const int* __restrict__ q,
                                                 const int* __restrict__ r) {
    __shared__ int2 sidx[LL];
    int bx = blockIdx.x, b = bx >> 1, h = bx & 1;
    int tid = threadIdx.x, wid = tid >> 5, lane = tid & 31;
    int mq = lane >> 3, cpi = lane & 7;

    for (int i = tid; i < LL; i += 128) {
        int qv = q[b*LL + i], rv = r[b*LL + i];
        sidx[i] = make_int2(qv*MSZ, (qv + NUM_C*rv)*64);
    }

    int eoff  = h*64 + wid*16 + cpi*2;
    int cpIdx = eoff >> 1;
    ull mv[16];
#pragma unroll
    for (int j = 0; j < 16; j++)
        mv[j] = *(const ull*)(Mv0 + (mq*16 + j)*DIM + eoff);
    __syncthreads();

    float* rb = g_read + (b*LL)*DIM + eoff;

    SD S[8];
#pragma unroll
    for (int i = 0; i < 8; i++) sd_load(S[i], sidx[i], mq, cpIdx);
    int2 nix = sidx[8];

    ull racc_p = 0ULL, s1_p = 0ULL, r2_p = 0ULL, s2_p = 0ULL;

    for (int l = 0; l < LL; l += 8) {
#pragma unroll
        for (int u = 0; u < 8; u++) {
            int lc = l + u;
            ull racc = scan_fma(S[u], mv);
            sd_load(S[u], nix, mq, cpIdx);
            int nl = lc + 9;
            nix = sidx[(nl < LL) ? nl : (LL - 1)];
            ull r2n = add2(racc_p, s1_p);
            ull s2n = __shfl_xor_sync(0xffffffffu, r2n, 16);
            ull fin = add2(r2_p, s2_p);
            if (lc >= 2 && mq == 0) *(ull*)(rb + (lc - 2)*DIM) = fin;
            ull s1n = __shfl_xor_sync(0xffffffffu, racc, 8);
            racc_p = racc; s1_p = s1n; r2_p = r2n; s2_p = s2n;
        }
    }
    ull r2n = add2(racc_p, s1_p);
    ull s2n = __shfl_xor_sync(0xffffffffu, r2n, 16);
    ull fin = add2(r2_p, s2_p);
    if (mq == 0) *(ull*)(rb + 510*DIM) = fin;
    fin = add2(r2n, s2n);
    if (mq == 0) *(ull*)(rb + 511*DIM) = fin;
}

// ======================================================================
// Kernel 3: f = tanh(read@Wf_r + fk), p = sigmoid(f.Wp + bp).
// r8 structure (2 bars, immediate epilogue, iter-ahead prefetch) with
// rr stored as PLAIN FLOATS (halves LDS count + crossbar bytes);
// pair duplication moved to pack2 MOVs at use (ALU pipe, free slots).
// ======================================================================
__global__ void __launch_bounds__(128, 2) k_fp(const int* __restrict__ q,
                                               const float* __restrict__ Wf,
                                               const float* __restrict__ Wp,
                                               const float* __restrict__ bp,
                                               float* __restrict__ out) {
    __shared__ __align__(16) float rr[8][DIM];          // [token][dim]       4KB
    __shared__ __align__(16) ulonglong2 part[8][4][32]; // [tok][iq][po]     16KB
    int tid = threadIdx.x;
    int iq = tid >> 5, po = tid & 31;
    int wid = iq, lane = po;

    ull wfA[32], wfB[32];
#pragma unroll
    for (int i = 0; i < 32; i++) {
        wfA[i] = *(const ull*)(Wf + (iq*32 + i)*DIM + 2*po);
        wfB[i] = *(const ull*)(Wf + (iq*32 + i)*DIM + 64 + 2*po);
    }
    float wp0 = Wp[2*lane],      wp1 = Wp[2*lane + 1];
    float wp2 = Wp[2*lane + 64], wp3 = Wp[2*lane + 65];
    float bpv = bp[0];

    const int stride = gridDim.x * 8;
    int tok0 = blockIdx.x * 8;

    float rv[8];
    ull fkA0 = 0ULL, fkA1 = 0ULL, fkB0 = 0ULL, fkB1 = 0ULL;
    if (tok0 < NTOK) {
#pragma unroll
        for (int tt = 0; tt < 8; tt++)
            rv[tt] = g_read[(tok0 + tt)*DIM + tid];
        int q0 = q[tok0 + 2*wid], q1 = q[tok0 + 2*wid + 1];
        fkA0 = *(const ull*)(g_fk + q0*DIM + 2*lane);
        fkA1 = *(const ull*)(g_fk + q0*DIM + 2*lane + 64);
        fkB0 = *(const ull*)(g_fk + q1*DIM + 2*lane);
        fkB1 = *(const ull*)(g_fk + q1*DIM + 2*lane + 64);
    }

    for (; tok0 < NTOK; tok0 += stride) {
#pragma unroll
        for (int tt = 0; tt < 8; tt++)
            rr[tt][tid] = rv[tt];
        __syncthreads();                               // A

        int tokn = tok0 + stride;
        float rvn[8];
        ull fkA0n = 0ULL, fkA1n = 0ULL, fkB0n = 0ULL, fkB1n = 0ULL;
        if (tokn < NTOK) {
#pragma unroll
            for (int tt = 0; tt < 8; tt++)
                rvn[tt] = g_read[(tokn + tt)*DIM + tid];
            int qn0 = q[tokn + 2*wid], qn1 = q[tokn + 2*wid + 1];
            fkA0n = *(const ull*)(g_fk + qn0*DIM + 2*lane);
            fkA1n = *(const ull*)(g_fk + qn0*DIM + 2*lane + 64);
            fkB0n = *(const ull*)(g_fk + qn1*DIM + 2*lane);
            fkB1n = *(const ull*)(g_fk + qn1*DIM + 2*lane + 64);
        } else {
#pragma unroll
            for (int tt = 0; tt < 8; tt++) rvn[tt] = 0.f;
        }

        // GEMV: 8 tokens, 32-dim slice per thread (8 float4 loads/token),
        // 2 output pairs per thread; dup pairs built by MOV at use.
        ull accA[8], accB[8];
#pragma unroll
        for (int tt = 0; tt < 8; tt++) { accA[tt] = 0ULL; accB[tt] = 0ULL; }
#pragma unroll
        for (int j = 0; j < 8; j++) {
#pragma unroll
            for (int tt = 0; tt < 8; tt++) {
                float4 v = ((const float4*)&rr[tt][iq*32])[j];
                ull d0 = pack2(v.x, v.x);
                ull d1 = pack2(v.y, v.y);
                ull d2 = pack2(v.z, v.z);
                ull d3 = pack2(v.w, v.w);
                accA[tt] = fma2(wfA[4*j + 0], d0, accA[tt]);
                accB[tt] = fma2(wfB[4*j + 0], d0, accB[tt]);
                accA[tt] = fma2(wfA[4*j + 1], d1, accA[tt]);
                accB[tt] = fma2(wfB[4*j + 1], d1, accB[tt]);
                accA[tt] = fma2(wfA[4*j + 2], d2, accA[tt]);
                accB[tt] = fma2(wfB[4*j + 2], d2, accB[tt]);
                accA[tt] = fma2(wfA[4*j + 3], d3, accA[tt]);
                accB[tt] = fma2(wfB[4*j + 3], d3, accB[tt]);
            }
        }
#pragma unroll
        for (int tt = 0; tt < 8; tt++) {
            ulonglong2 pr; pr.x = accA[tt]; pr.y = accB[tt];
            part[tt][iq][po] = pr;
        }
        __syncthreads();                               // B

        {
            int t0 = 2*wid, t1 = t0 + 1;
            ull sA0 = fkA0, sA1 = fkA1, sB0 = fkB0, sB1 = fkB1;
#pragma unroll
            for (int g4 = 0; g4 < 4; g4++) {
                ulonglong2 p0 = part[t0][g4][lane];
                ulonglong2 p1 = part[t1][g4][lane];
                sA0 = add2(sA0, p0.x);
                sA1 = add2(sA1, p0.y);
                sB0 = add2(sB0, p1.x);
                sB1 = add2(sB1, p1.y);
            }
            float2 a0 = unpack2(sA0), a1 = unpack2(sA1);
            float2 b0 = unpack2(sB0), b1 = unpack2(sB1);
            float pvA = fmaf(tanh_fast(a0.x), wp0,
                        fmaf(tanh_fast(a0.y), wp1,
                        fmaf(tanh_fast(a1.x), wp2, tanh_fast(a1.y) * wp3)));
            float pvB = fmaf(tanh_fast(b0.x), wp0,
                        fmaf(tanh_fast(b0.y), wp1,
                        fmaf(tanh_fast(b1.x), wp2, tanh_fast(b1.y) * wp3)));
#pragma unroll
            for (int o = 16; o > 0; o >>= 1) {
                pvA += __shfl_xor_sync(0xffffffffu, pvA, o);
                pvB += __shfl_xor_sync(0xffffffffu, pvB, o);
            }
            if (lane == 0) {
                out[tok0 + t0] = sigmoid_fast(pvA + bpv);
                out[tok0 + t1] = sigmoid_fast(pvB + bpv);
            }
        }

#pragma unroll
        for (int tt = 0; tt < 8; tt++) rv[tt] = rvn[tt];
        fkA0 = fkA0n; fkA1 = fkA1n; fkB0 = fkB0n; fkB1 = fkB1n;
    }
}

// ---------------- launch ----------------
extern "C" void kernel_launch(void* const* d_in, const int* in_sizes, int n_in,
                              void* d_out, int out_size) {
    const int*   q   = (const int*)d_in[0];
    const int*   r   = (const int*)d_in[1];
    const float* Ek  = (const float*)d_in[2];
    const float* Ev  = (const float*)d_in[3];
    const float* Mk  = (const float*)d_in[4];
    const float* Mv0 = (const float*)d_in[5];
    const float* We  = (const float*)d_in[6];
    const float* be  = (const float*)d_in[7];
    const float* Wa  = (const float*)d_in[8];
    const float* ba  = (const float*)d_in[9];
    const float* Wf  = (const float*)d_in[10];
    const float* bf  = (const float*)d_in[11];
    const float* Wp  = (const float*)d_in[12];
    const float* bp  = (const float*)d_in[13];
    float* out = (float*)d_out;

    k_wtab<<<WT_BLOCKS, 128>>>(Ek, Mk);
    k_cgemm<<<250, 128>>>(Ek, Ev, We, be, Wa, ba, Wf, bf);
    k_scan<<<2*BB, 128>>>(Mv0, q, r);
    k_fp<<<296, 128>>>(q, Wf, Wp, bp, out);
}